// round 3
// baseline (speedup 1.0000x reference)
#include <cuda_runtime.h>

#define F_CNT 256
#define IMG   256
#define V_CNT 1024

// Per-face precomputed data:
// 0:ax 1:ay 2:bx 3:by 4:cx 5:cy 6:Asafe 7:zi0 8:zi1 9:zi2
// 10:u0 11:v0 12:u1 13:v1 14:u2 15:v2
__device__ float g_face[F_CNT][16];
__device__ int   g_bbox[F_CNT][4];  // jlo, jhi, ilo, ihi (empty if invalid)
__device__ float g_zinit;

// linspace(-1,1,256)[k]: XLA lowers start + iota*step and LLVM contracts to
// fma(k, step, -1). Endpoint exact (numpy-compat endpoint=True).
__device__ __forceinline__ float lin_at(int k) {
    const float STEP = 2.0f / 255.0f;  // fp32-rounded step
    if (k == 255) return 1.0f;
    return __fmaf_rn((float)k, STEP, -1.0f);
}

__device__ __forceinline__ long long load_idx(const void* buf, int i, int is64) {
    if (is64) return ((const long long*)buf)[i];
    return (long long)(((const int*)buf)[i]);
}

__global__ void prep_kernel(const float* __restrict__ vertices,
                            const void* __restrict__ faces,
                            const float* __restrict__ uv,
                            const void* __restrict__ uvfaces)
{
    int f = threadIdx.x;

    __shared__ float sz[256];
    __shared__ int s_f64, s_u64;

    // dtype probe: if int64, high (odd) 32-bit words of first 384 entries are 0.
    // Reading 768 words is in-bounds for both int32 (768 words) and int64 (1536 words).
    if (f == 0) {
        const unsigned* wf = (const unsigned*)faces;
        const unsigned* wu = (const unsigned*)uvfaces;
        unsigned af = 0, au = 0;
        for (int q = 0; q < 384; q++) { af |= wf[2 * q + 1]; au |= wu[2 * q + 1]; }
        s_f64 = (af == 0) ? 1 : 0;
        s_u64 = (au == 0) ? 1 : 0;
    }

    // min-z reduction over all vertices
    float zm = 3.0e38f;
    for (int v = f; v < V_CNT; v += 256) zm = fminf(zm, vertices[v * 3 + 2]);
    sz[f] = zm;
    __syncthreads();
    for (int off = 128; off > 0; off >>= 1) {
        if (f < off) sz[f] = fminf(sz[f], sz[f + off]);
        __syncthreads();
    }
    if (f == 0) g_zinit = sz[0];

    int is_f64 = s_f64, is_u64 = s_u64;

    long long i0 = load_idx(faces, f * 3 + 0, is_f64);
    long long i1 = load_idx(faces, f * 3 + 1, is_f64);
    long long i2 = load_idx(faces, f * 3 + 2, is_f64);

    float ax = vertices[i0 * 3 + 0], ay = vertices[i0 * 3 + 1], az = vertices[i0 * 3 + 2];
    float bx = vertices[i1 * 3 + 0], by = vertices[i1 * 3 + 1], bz = vertices[i1 * 3 + 2];
    float cx = vertices[i2 * 3 + 0], cy = vertices[i2 * 3 + 1], cz = vertices[i2 * 3 + 2];

    // signed 2D area, LLVM-contracted: fma(d1, d2, -(d3*d4))
    float A = __fmaf_rn(__fsub_rn(bx, ax), __fsub_rn(cy, ay),
                        -__fmul_rn(__fsub_rn(by, ay), __fsub_rn(cx, ax)));
    bool valid = (A >= 1e-9f);
    float Asafe = (fabsf(A) < 1e-9f) ? 1.0f : A;

    float zi0 = __fdiv_rn(1.0f, az);
    float zi1 = __fdiv_rn(1.0f, bz);
    float zi2 = __fdiv_rn(1.0f, cz);

    long long j0 = load_idx(uvfaces, f * 3 + 0, is_u64);
    long long j1 = load_idx(uvfaces, f * 3 + 1, is_u64);
    long long j2 = load_idx(uvfaces, f * 3 + 2, is_u64);

    // uvn = uv*2 - 1 contracts to fma(uv, 2, -1); then * z_inv
    float u0 = __fmul_rn(__fmaf_rn(uv[j0 * 2 + 0], 2.0f, -1.0f), zi0);
    float v0 = __fmul_rn(__fmaf_rn(uv[j0 * 2 + 1], 2.0f, -1.0f), zi0);
    float u1 = __fmul_rn(__fmaf_rn(uv[j1 * 2 + 0], 2.0f, -1.0f), zi1);
    float v1 = __fmul_rn(__fmaf_rn(uv[j1 * 2 + 1], 2.0f, -1.0f), zi1);
    float u2 = __fmul_rn(__fmaf_rn(uv[j2 * 2 + 0], 2.0f, -1.0f), zi2);
    float v2 = __fmul_rn(__fmaf_rn(uv[j2 * 2 + 1], 2.0f, -1.0f), zi2);

    float* fd = g_face[f];
    fd[0] = ax; fd[1] = ay; fd[2] = bx; fd[3] = by; fd[4] = cx; fd[5] = cy;
    fd[6] = Asafe;
    fd[7] = zi0; fd[8] = zi1; fd[9] = zi2;
    fd[10] = u0; fd[11] = v0; fd[12] = u1; fd[13] = v1; fd[14] = u2; fd[15] = v2;

    // conservative pixel bbox (±1 pixel margin)
    int jlo = 1, jhi = 0, ilo = 1, ihi = 0;
    if (valid) {
        float minx = fminf(ax, fminf(bx, cx)), maxx = fmaxf(ax, fmaxf(bx, cx));
        float miny = fminf(ay, fminf(by, cy)), maxy = fmaxf(ay, fmaxf(by, cy));
        jlo = max(0,   (int)floorf((minx + 1.0f) * 127.5f) - 1);
        jhi = min(255, (int)ceilf ((maxx + 1.0f) * 127.5f) + 1);
        int klo = max(0,   (int)floorf((miny + 1.0f) * 127.5f) - 1);
        int khi = min(255, (int)ceilf ((maxy + 1.0f) * 127.5f) + 1);
        ilo = 255 - khi;
        ihi = 255 - klo;
    }
    g_bbox[f][0] = jlo; g_bbox[f][1] = jhi; g_bbox[f][2] = ilo; g_bbox[f][3] = ihi;
}

__global__ void __launch_bounds__(256) raster_kernel(const float* __restrict__ uvmap,
                                                     float* __restrict__ out)
{
    __shared__ float sd[16][F_CNT];
    __shared__ int warpcnt[8];
    __shared__ int warpoff[8];
    __shared__ int s_count;

    int tx = threadIdx.x, ty = threadIdx.y;
    int t = ty * 16 + tx;
    int jt0 = blockIdx.x * 16;
    int it0 = blockIdx.y * 16;

    // --- stable (index-order-preserving) compaction of tile-overlapping faces ---
    const int* bb = g_bbox[t];
    int b0 = bb[0], b1 = bb[1], b2 = bb[2], b3 = bb[3];
    bool flag = (b0 <= jt0 + 15) && (b1 >= jt0) && (b2 <= it0 + 15) && (b3 >= it0);

    unsigned mask = __ballot_sync(0xffffffffu, flag);
    int warp = t >> 5, lane = t & 31;
    if (lane == 0) warpcnt[warp] = __popc(mask);
    __syncthreads();
    if (t == 0) {
        int acc = 0;
        #pragma unroll
        for (int w = 0; w < 8; w++) { warpoff[w] = acc; acc += warpcnt[w]; }
        s_count = acc;
    }
    __syncthreads();
    if (flag) {
        int pos = warpoff[warp] + __popc(mask & ((1u << lane) - 1u));
        const float* fd = g_face[t];
        #pragma unroll
        for (int q = 0; q < 16; q++) sd[q][pos] = fd[q];
    }
    __syncthreads();

    int nf = s_count;
    float zinit = g_zinit;

    int j = jt0 + tx, i = it0 + ty;
    float px = lin_at(j);
    float py = lin_at(255 - i);   // pts from rot90: py = lin[255-i]

    float best = __int_as_float(0xff800000);  // -inf
    int bk = -1;
    float bw1 = 0.f, bw2 = 0.f, bw3 = 0.f;

    for (int k = 0; k < nf; k++) {
        float ax = sd[0][k], ay = sd[1][k];
        float bx = sd[2][k], by = sd[3][k];
        float cx = sd[4][k], cyv = sd[5][k];

        // edge(a,c) = (px-ax)*(cy-ay) - (py-ay)*(cx-ax)
        // LLVM contraction: fsub(fmul m1, m2) -> fma(m1.a, m1.b, -m2)
        float pAB = __fmaf_rn(__fsub_rn(px, bx), __fsub_rn(ay, by),
                              -__fmul_rn(__fsub_rn(py, by), __fsub_rn(ax, bx)));
        float pCB = __fmaf_rn(__fsub_rn(px, cx), __fsub_rn(by, cyv),
                              -__fmul_rn(__fsub_rn(py, cyv), __fsub_rn(bx, cx)));
        float pCA = __fmaf_rn(__fsub_rn(px, ax), __fsub_rn(cyv, ay),
                              -__fmul_rn(__fsub_rn(py, ay), __fsub_rn(cx, ax)));

        if (pAB > 0.0f && pCB > 0.0f && pCA > 0.0f) {
            float Asafe = sd[6][k];
            float w1 = __fdiv_rn(pCB, Asafe);
            float w2 = __fdiv_rn(pCA, Asafe);
            float w3 = __fsub_rn(__fsub_rn(1.0f, w1), w2);
            // ((w1*z0 + w2*z1) + w3*z2) contracts to fma(w3,z2, fma(w1,z0, w2*z1))
            float zinv = __fmaf_rn(w3, sd[9][k],
                         __fmaf_rn(w1, sd[7][k],
                         __fmul_rn(w2, sd[8][k])));
            float Z = __fdiv_rn(1.0f, zinv);
            // score = Z if Z >= zinit else -inf; argmax keeps FIRST max -> strict >
            if (Z >= zinit && Z > best) {
                best = Z; bk = k; bw1 = w1; bw2 = w2; bw3 = w3;
            }
        }
    }

    float r = 0.f, g = 0.f, b = 0.f, h = 0.f;
    if (bk >= 0) {
        h = 1.0f;
        float Zw = best;  // 1/zinv at winner, bit-identical to ref's Zw

        // ((W1*u0 + W2*u1) + W3*u2) -> fma(W3,u2, fma(W1,u0, W2*u1))
        float u = __fmaf_rn(bw3, sd[14][bk],
                  __fmaf_rn(bw1, sd[10][bk],
                  __fmul_rn(bw2, sd[12][bk])));
        float v = __fmaf_rn(bw3, sd[15][bk],
                  __fmaf_rn(bw1, sd[11][bk],
                  __fmul_rn(bw2, sd[13][bk])));
        float gx = __fmul_rn(u, Zw);
        float gy = __fmul_rn(v, Zw);

        // x = ((gx+1)*W - 1)*0.5 ; (gx+1)*256 - 1 contracts to fma(gx+1, 256, -1)
        float x = __fmul_rn(__fmaf_rn(__fadd_rn(gx, 1.0f), 256.0f, -1.0f), 0.5f);
        float y = __fmul_rn(__fmaf_rn(__fadd_rn(gy, 1.0f), 256.0f, -1.0f), 0.5f);
        float x0 = floorf(x), y0 = floorf(y);
        float x1 = __fadd_rn(x0, 1.0f), y1 = __fadd_rn(y0, 1.0f);
        float wx1 = __fsub_rn(x, x0), wx0 = __fsub_rn(1.0f, wx1);
        float wy1 = __fsub_rn(y, y0), wy0 = __fsub_rn(1.0f, wy1);

        bool v00 = (x0 >= 0.f) && (x0 <= 255.f) && (y0 >= 0.f) && (y0 <= 255.f);
        bool v10 = (x1 >= 0.f) && (x1 <= 255.f) && (y0 >= 0.f) && (y0 <= 255.f);
        bool v01 = (x0 >= 0.f) && (x0 <= 255.f) && (y1 >= 0.f) && (y1 <= 255.f);
        bool v11 = (x1 >= 0.f) && (x1 <= 255.f) && (y1 >= 0.f) && (y1 <= 255.f);

        int ix0 = (int)fminf(fmaxf(x0, 0.f), 255.f);
        int ix1 = (int)fminf(fmaxf(x1, 0.f), 255.f);
        int iy0 = (int)fminf(fmaxf(y0, 0.f), 255.f);
        int iy1 = (int)fminf(fmaxf(y1, 0.f), 255.f);

        float w00 = __fmul_rn(wx0, wy0);
        float w10 = __fmul_rn(wx1, wy0);
        float w01 = __fmul_rn(wx0, wy1);
        float w11 = __fmul_rn(wx1, wy1);

        int o00 = iy0 * 256 + ix0;
        int o10 = iy0 * 256 + ix1;
        int o01 = iy1 * 256 + ix0;
        int o11 = iy1 * 256 + ix1;

        float acc[3];
        #pragma unroll
        for (int c = 0; c < 3; c++) {
            const float* img = uvmap + c * 65536;
            float t00 = v00 ? img[o00] : 0.f;
            float t10 = v10 ? img[o10] : 0.f;
            float t01 = v01 ? img[o01] : 0.f;
            float t11 = v11 ? img[o11] : 0.f;
            // (((g00*w00 + g10*w10) + g01*w01) + g11*w11) contraction order:
            // fma(g11,w11, fma(g01,w01, fma(g00,w00, g10*w10)))
            acc[c] = __fmaf_rn(t11, w11,
                     __fmaf_rn(t01, w01,
                     __fmaf_rn(t00, w00,
                     __fmul_rn(t10, w10))));
        }
        r = acc[0]; g = acc[1]; b = acc[2];
    }

    int pidx = i * 256 + j;
    out[0 * 65536 + pidx] = r;
    out[1 * 65536 + pidx] = g;
    out[2 * 65536 + pidx] = b;
    out[3 * 65536 + pidx] = h;
}

extern "C" void kernel_launch(void* const* d_in, const int* in_sizes, int n_in,
                              void* d_out, int out_size)
{
    const float* vertices = (const float*)d_in[0];
    const void*  faces    = d_in[1];
    const float* uv       = (const float*)d_in[2];
    const void*  uvfaces  = d_in[3];
    const float* uvmap    = (const float*)d_in[4];
    float* out = (float*)d_out;

    prep_kernel<<<1, 256>>>(vertices, faces, uv, uvfaces);
    dim3 blk(16, 16), grd(IMG / 16, IMG / 16);
    raster_kernel<<<grd, blk>>>(uvmap, out);
}

// round 5
// speedup vs baseline: 2.0239x; 2.0239x over previous
#include <cuda_runtime.h>

#define IMG   256
#define F_CNT 256
#define V_CNT 1024

// linspace(-1,1,256)[k]: XLA lowers start + iota*step, LLVM contracts to
// fma(k, step, -1). Endpoint exact.
__device__ __forceinline__ float lin_at(int k) {
    const float STEP = 2.0f / 255.0f;
    if (k == 255) return 1.0f;
    return __fmaf_rn((float)k, STEP, -1.0f);
}

__global__ void __launch_bounds__(1024, 2) render_kernel(
    const float* __restrict__ vertices,
    const void*  __restrict__ faces,
    const float* __restrict__ uv,
    const void*  __restrict__ uvfaces,
    const float* __restrict__ uvmap,
    float*       __restrict__ out)
{
    // face data: 0:ax 1:ay 2:bx 3:by 4:cx 5:cy 6:Asafe 7:zi0 8:zi1 9:zi2
    //            10:u0 11:v0 12:u1 13:v1 14:u2 15:v2
    __shared__ float sd[16][F_CNT];
    __shared__ unsigned long long skey[4][256];
    __shared__ float s_warpmin[32];
    __shared__ unsigned char s_anyf[32], s_anyu[32];
    __shared__ float s_zinit;
    __shared__ int s_isf64, s_isu64;
    __shared__ int warpcnt[8], warpoff[8], s_count;

    const int tx = threadIdx.x, ty = threadIdx.y, tz = threadIdx.z;
    const int tid  = tx + ty * 16 + tz * 256;
    const int wid  = tid >> 5, lane = tid & 31;
    const int jt0 = blockIdx.x * 16, it0 = blockIdx.y * 16;

    // ---- phase 0: min-z reduce (all 1024 threads, 1 vertex each) ----
    float zm = vertices[tid * 3 + 2];
    #pragma unroll
    for (int o = 16; o; o >>= 1) zm = fminf(zm, __shfl_xor_sync(0xffffffffu, zm, o));
    if (lane == 0) s_warpmin[wid] = zm;

    // ---- dtype probe: high words of first 384 int64 entries are 0.
    // Reading 768 words is in-bounds for both int32 (768 w) and int64 (1536 w).
    unsigned pw = 0;
    if (wid < 12)       pw = ((const unsigned*)faces)[2 * tid + 1];
    else if (wid < 24)  pw = ((const unsigned*)uvfaces)[2 * (tid - 384) + 1];
    bool anyv = __any_sync(0xffffffffu, pw != 0u);
    if (lane == 0) {
        s_anyf[wid] = (wid < 12) && anyv;
        s_anyu[wid] = (wid >= 12 && wid < 24) && anyv;
    }
    __syncthreads();
    if (tid == 0) {
        float z = s_warpmin[0]; int af = 0, au = 0;
        #pragma unroll
        for (int w = 0; w < 32; w++) { z = fminf(z, s_warpmin[w]); af |= s_anyf[w]; au |= s_anyu[w]; }
        s_zinit = z; s_isf64 = !af; s_isu64 = !au;
    }
    __syncthreads();

    // ---- phase 1: per-face precompute + tile-overlap flag (threads 0..255) ----
    float fd[16];
    bool flag = false;
    if (tid < 256) {
        const int f = tid;
        long long i0, i1, i2, j0, j1, j2;
        if (s_isf64) {
            const long long* p = (const long long*)faces;
            i0 = p[f*3]; i1 = p[f*3+1]; i2 = p[f*3+2];
        } else {
            const int* p = (const int*)faces;
            i0 = p[f*3]; i1 = p[f*3+1]; i2 = p[f*3+2];
        }
        if (s_isu64) {
            const long long* p = (const long long*)uvfaces;
            j0 = p[f*3]; j1 = p[f*3+1]; j2 = p[f*3+2];
        } else {
            const int* p = (const int*)uvfaces;
            j0 = p[f*3]; j1 = p[f*3+1]; j2 = p[f*3+2];
        }

        float ax = vertices[i0*3+0], ay = vertices[i0*3+1], az = vertices[i0*3+2];
        float bx = vertices[i1*3+0], by = vertices[i1*3+1], bz = vertices[i1*3+2];
        float cx = vertices[i2*3+0], cy = vertices[i2*3+1], cz = vertices[i2*3+2];

        // signed 2D area, LLVM-contracted: fma(d1, d2, -(d3*d4))
        float A = __fmaf_rn(__fsub_rn(bx, ax), __fsub_rn(cy, ay),
                            -__fmul_rn(__fsub_rn(by, ay), __fsub_rn(cx, ax)));
        float Asafe = (fabsf(A) < 1e-9f) ? 1.0f : A;

        float zi0 = __fdiv_rn(1.0f, az);
        float zi1 = __fdiv_rn(1.0f, bz);
        float zi2 = __fdiv_rn(1.0f, cz);

        // uvn = uv*2 - 1 contracts to fma(uv,2,-1); then * z_inv
        float u0 = __fmul_rn(__fmaf_rn(uv[j0*2+0], 2.0f, -1.0f), zi0);
        float v0 = __fmul_rn(__fmaf_rn(uv[j0*2+1], 2.0f, -1.0f), zi0);
        float u1 = __fmul_rn(__fmaf_rn(uv[j1*2+0], 2.0f, -1.0f), zi1);
        float v1 = __fmul_rn(__fmaf_rn(uv[j1*2+1], 2.0f, -1.0f), zi1);
        float u2 = __fmul_rn(__fmaf_rn(uv[j2*2+0], 2.0f, -1.0f), zi2);
        float v2 = __fmul_rn(__fmaf_rn(uv[j2*2+1], 2.0f, -1.0f), zi2);

        fd[0]=ax; fd[1]=ay; fd[2]=bx; fd[3]=by; fd[4]=cx; fd[5]=cy;
        fd[6]=Asafe; fd[7]=zi0; fd[8]=zi1; fd[9]=zi2;
        fd[10]=u0; fd[11]=v0; fd[12]=u1; fd[13]=v1; fd[14]=u2; fd[15]=v2;

        if (A >= 1e-9f) {
            float minx = fminf(ax, fminf(bx, cx)), maxx = fmaxf(ax, fmaxf(bx, cx));
            float miny = fminf(ay, fminf(by, cy)), maxy = fmaxf(ay, fmaxf(by, cy));
            int jlo = max(0,   (int)floorf((minx + 1.0f) * 127.5f) - 1);
            int jhi = min(255, (int)ceilf ((maxx + 1.0f) * 127.5f) + 1);
            int klo = max(0,   (int)floorf((miny + 1.0f) * 127.5f) - 1);
            int khi = min(255, (int)ceilf ((maxy + 1.0f) * 127.5f) + 1);
            int ilo = 255 - khi, ihi = 255 - klo;
            flag = (jlo <= jt0 + 15) && (jhi >= jt0) && (ilo <= it0 + 15) && (ihi >= it0);
        }
    }

    // ---- stable (index-order) compaction into sd ----
    unsigned bmask = 0;
    if (wid < 8) {
        bmask = __ballot_sync(0xffffffffu, flag);
        if (lane == 0) warpcnt[wid] = __popc(bmask);
    }
    __syncthreads();
    if (tid == 0) {
        int acc = 0;
        #pragma unroll
        for (int w = 0; w < 8; w++) { warpoff[w] = acc; acc += warpcnt[w]; }
        s_count = acc;
    }
    __syncthreads();
    if (flag) {
        int pos = warpoff[wid] + __popc(bmask & ((1u << lane) - 1u));
        #pragma unroll
        for (int q = 0; q < 16; q++) sd[q][pos] = fd[q];
    }
    __syncthreads();

    // ---- main loop: thread tz scans faces k = tz, tz+4, ... ----
    const int nf = s_count;
    const float zinit = s_zinit;
    const int j = jt0 + tx, i = it0 + ty;
    const float px = lin_at(j);
    const float py = lin_at(255 - i);   // rot90: py = lin[255-i]

    unsigned long long bestkey = 0ull;
    for (int k = tz; k < nf; k += 4) {
        float ax = sd[0][k], ay = sd[1][k];
        float bx = sd[2][k], by = sd[3][k];
        float cx = sd[4][k], cyv = sd[5][k];

        // edge(a,c) = (px-ax)*(cy-ay) - (py-ay)*(cx-ax)
        // LLVM contraction: fma(m1a, m1b, -(m2a*m2b))
        float pAB = __fmaf_rn(__fsub_rn(px, bx), __fsub_rn(ay, by),
                              -__fmul_rn(__fsub_rn(py, by), __fsub_rn(ax, bx)));
        float pCB = __fmaf_rn(__fsub_rn(px, cx), __fsub_rn(by, cyv),
                              -__fmul_rn(__fsub_rn(py, cyv), __fsub_rn(bx, cx)));
        float pCA = __fmaf_rn(__fsub_rn(px, ax), __fsub_rn(cyv, ay),
                              -__fmul_rn(__fsub_rn(py, ay), __fsub_rn(cx, ax)));

        if (pAB > 0.0f && pCB > 0.0f && pCA > 0.0f) {
            float Asafe = sd[6][k];
            float w1 = __fdiv_rn(pCB, Asafe);
            float w2 = __fdiv_rn(pCA, Asafe);
            float w3 = __fsub_rn(__fsub_rn(1.0f, w1), w2);
            float zinv = __fmaf_rn(w3, sd[9][k],
                         __fmaf_rn(w1, sd[7][k],
                         __fmul_rn(w2, sd[8][k])));
            float Z = __fdiv_rn(1.0f, zinv);
            // score = Z if Z >= zinit; cover => zinv in (0.5,2) so Z finite > 0.
            // key: max Z wins, ties -> smaller k (argmax-first semantics).
            if (Z >= zinit) {
                unsigned long long key =
                    ((unsigned long long)__float_as_uint(Z) << 32) | (unsigned)(255 - k);
                if (key > bestkey) bestkey = key;
            }
        }
    }
    skey[tz][ty * 16 + tx] = bestkey;
    __syncthreads();

    // ---- epilogue: tz==0 combines 4 splits, shades, stores ----
    if (tz == 0) {
        int pix = ty * 16 + tx;
        unsigned long long key = skey[0][pix];
        unsigned long long k1 = skey[1][pix]; if (k1 > key) key = k1;
        unsigned long long k2 = skey[2][pix]; if (k2 > key) key = k2;
        unsigned long long k3 = skey[3][pix]; if (k3 > key) key = k3;

        float r = 0.f, g = 0.f, b = 0.f, h = 0.f;
        if (key != 0ull) {
            h = 1.0f;
            int bk = 255 - (int)(key & 0xFFull);
            float Zw = __uint_as_float((unsigned)(key >> 32));  // bit-exact winner Z

            float ax = sd[0][bk], ay = sd[1][bk];
            float bx = sd[2][bk], by = sd[3][bk];
            float cx = sd[4][bk], cyv = sd[5][bk];
            float pCB = __fmaf_rn(__fsub_rn(px, cx), __fsub_rn(by, cyv),
                                  -__fmul_rn(__fsub_rn(py, cyv), __fsub_rn(bx, cx)));
            float pCA = __fmaf_rn(__fsub_rn(px, ax), __fsub_rn(cyv, ay),
                                  -__fmul_rn(__fsub_rn(py, ay), __fsub_rn(cx, ax)));
            float Asafe = sd[6][bk];
            float w1 = __fdiv_rn(pCB, Asafe);
            float w2 = __fdiv_rn(pCA, Asafe);
            float w3 = __fsub_rn(__fsub_rn(1.0f, w1), w2);

            float u = __fmaf_rn(w3, sd[14][bk],
                      __fmaf_rn(w1, sd[10][bk],
                      __fmul_rn(w2, sd[12][bk])));
            float v = __fmaf_rn(w3, sd[15][bk],
                      __fmaf_rn(w1, sd[11][bk],
                      __fmul_rn(w2, sd[13][bk])));
            float gx = __fmul_rn(u, Zw);
            float gy = __fmul_rn(v, Zw);

            // x = ((gx+1)*256 - 1)*0.5, contracted to fma(gx+1, 256, -1)
            float x = __fmul_rn(__fmaf_rn(__fadd_rn(gx, 1.0f), 256.0f, -1.0f), 0.5f);
            float y = __fmul_rn(__fmaf_rn(__fadd_rn(gy, 1.0f), 256.0f, -1.0f), 0.5f);
            float x0 = floorf(x), y0 = floorf(y);
            float x1 = __fadd_rn(x0, 1.0f), y1 = __fadd_rn(y0, 1.0f);
            float wx1 = __fsub_rn(x, x0), wx0 = __fsub_rn(1.0f, wx1);
            float wy1 = __fsub_rn(y, y0), wy0 = __fsub_rn(1.0f, wy1);

            bool v00 = (x0 >= 0.f) && (x0 <= 255.f) && (y0 >= 0.f) && (y0 <= 255.f);
            bool v10 = (x1 >= 0.f) && (x1 <= 255.f) && (y0 >= 0.f) && (y0 <= 255.f);
            bool v01 = (x0 >= 0.f) && (x0 <= 255.f) && (y1 >= 0.f) && (y1 <= 255.f);
            bool v11 = (x1 >= 0.f) && (x1 <= 255.f) && (y1 >= 0.f) && (y1 <= 255.f);

            int ix0 = (int)fminf(fmaxf(x0, 0.f), 255.f);
            int ix1 = (int)fminf(fmaxf(x1, 0.f), 255.f);
            int iy0 = (int)fminf(fmaxf(y0, 0.f), 255.f);
            int iy1 = (int)fminf(fmaxf(y1, 0.f), 255.f);

            float w00 = __fmul_rn(wx0, wy0);
            float w10 = __fmul_rn(wx1, wy0);
            float w01 = __fmul_rn(wx0, wy1);
            float w11 = __fmul_rn(wx1, wy1);

            int o00 = iy0 * 256 + ix0, o10 = iy0 * 256 + ix1;
            int o01 = iy1 * 256 + ix0, o11 = iy1 * 256 + ix1;

            float acc[3];
            #pragma unroll
            for (int c = 0; c < 3; c++) {
                const float* img = uvmap + c * 65536;
                float t00 = v00 ? __ldg(img + o00) : 0.f;
                float t10 = v10 ? __ldg(img + o10) : 0.f;
                float t01 = v01 ? __ldg(img + o01) : 0.f;
                float t11 = v11 ? __ldg(img + o11) : 0.f;
                acc[c] = __fmaf_rn(t11, w11,
                         __fmaf_rn(t01, w01,
                         __fmaf_rn(t00, w00,
                         __fmul_rn(t10, w10))));
            }
            r = acc[0]; g = acc[1]; b = acc[2];
        }

        int pidx = i * 256 + j;
        out[0 * 65536 + pidx] = r;
        out[1 * 65536 + pidx] = g;
        out[2 * 65536 + pidx] = b;
        out[3 * 65536 + pidx] = h;
    }
}

extern "C" void kernel_launch(void* const* d_in, const int* in_sizes, int n_in,
                              void* d_out, int out_size)
{
    const float* vertices = (const float*)d_in[0];
    const void*  faces    = d_in[1];
    const float* uv       = (const float*)d_in[2];
    const void*  uvfaces  = d_in[3];
    const float* uvmap    = (const float*)d_in[4];
    float* out = (float*)d_out;

    dim3 blk(16, 16, 4), grd(IMG / 16, IMG / 16);
    render_kernel<<<grd, blk>>>(vertices, faces, uv, uvfaces, uvmap, out);
}

// round 6
// speedup vs baseline: 2.7644x; 1.3659x over previous
#include <cuda_runtime.h>

#define IMG   256
#define F_CNT 256
#define V_CNT 1024

// linspace(-1,1,256)[k]: XLA lowers start + iota*step, LLVM contracts to
// fma(k, step, -1). Endpoint exact.
__device__ __forceinline__ float lin_at(int k) {
    const float STEP = 2.0f / 255.0f;
    if (k == 255) return 1.0f;
    return __fmaf_rn((float)k, STEP, -1.0f);
}

// edge value at (qx,qy) for edge anchored at (ex,ey) with precomputed deltas:
// E = fma(qx-ex, dy, -((qy-ey)*dx))   (bit-identical to reference contraction)
__device__ __forceinline__ float edge_at(float qx, float qy, float ex, float ey,
                                         float dy, float dx) {
    return __fmaf_rn(__fsub_rn(qx, ex), dy, -__fmul_rn(__fsub_rn(qy, ey), dx));
}

__global__ void __launch_bounds__(1024, 2) render_kernel(
    const float* __restrict__ vertices,
    const void*  __restrict__ faces,
    const float* __restrict__ uv,
    const void*  __restrict__ uvfaces,
    const float* __restrict__ uvmap,
    float*       __restrict__ out)
{
    // per-face packed data (compacted, tile-local):
    // [0] = (bx, by, ay-by, ax-bx)   edge AB
    // [1] = (cx, cy, by-cy, bx-cx)   edge CB
    // [2] = (ax, ay, cy-ay, cx-ax)   edge CA
    // [3] = (Asafe, zi0, zi1, zi2)
    // [4] = (u0, v0, u1, v1)
    // [5] = (u2, v2, -, -)
    __shared__ float4 sf[F_CNT][6];
    __shared__ unsigned long long skey[4][256];
    __shared__ float s_warpmin[32];
    __shared__ unsigned char s_anyf[32], s_anyu[32];
    __shared__ float s_tthr;
    __shared__ int s_isf64, s_isu64;
    __shared__ int warpcnt[8], warpoff[8], s_count;

    const int tx = threadIdx.x, ty = threadIdx.y, tz = threadIdx.z;
    const int tid  = tx + ty * 16 + tz * 256;
    const int wid  = tid >> 5, lane = tid & 31;
    const int jt0 = blockIdx.x * 16, it0 = blockIdx.y * 16;

    // ---- phase 0: min-z reduce (1024 threads, 1 vertex each) ----
    float zm = vertices[tid * 3 + 2];
    #pragma unroll
    for (int o = 16; o; o >>= 1) zm = fminf(zm, __shfl_xor_sync(0xffffffffu, zm, o));
    if (lane == 0) s_warpmin[wid] = zm;

    // ---- dtype probe: high words of first 384 int64 entries are 0.
    // Reading 768 words is in-bounds for both int32 (768 w) and int64 (1536 w).
    unsigned pw = 0;
    if (wid < 12)       pw = ((const unsigned*)faces)[2 * tid + 1];
    else if (wid < 24)  pw = ((const unsigned*)uvfaces)[2 * (tid - 384) + 1];
    bool anyv = __any_sync(0xffffffffu, pw != 0u);
    if (lane == 0) {
        s_anyf[wid] = (wid < 12) && anyv;
        s_anyu[wid] = (wid >= 12 && wid < 24) && anyv;
    }
    __syncthreads();
    if (tid == 0) {
        float z = s_warpmin[0]; int af = 0, au = 0;
        #pragma unroll
        for (int w = 0; w < 32; w++) { z = fminf(z, s_warpmin[w]); af |= s_anyf[w]; au |= s_anyu[w]; }
        s_isf64 = !af; s_isu64 = !au;
        // t* = max { t : fdiv(1,t) >= zinit }, so (Z >= zinit) <=> (zinv <= t*).
        float t = __fdiv_rn(1.0f, z);
        if (__fdiv_rn(1.0f, t) >= z) {
            for (int it = 0; it < 4; ++it) {
                float tu = __uint_as_float(__float_as_uint(t) + 1u);
                if (__fdiv_rn(1.0f, tu) >= z) t = tu; else break;
            }
        } else {
            for (int it = 0; it < 4; ++it) {
                t = __uint_as_float(__float_as_uint(t) - 1u);
                if (__fdiv_rn(1.0f, t) >= z) break;
            }
        }
        s_tthr = t;
    }
    __syncthreads();

    // ---- phase 1: per-face precompute + tile cull (threads 0..255) ----
    float4 fd[6];
    bool flag = false;
    if (tid < 256) {
        const int f = tid;
        long long i0, i1, i2, j0, j1, j2;
        if (s_isf64) {
            const long long* p = (const long long*)faces;
            i0 = p[f*3]; i1 = p[f*3+1]; i2 = p[f*3+2];
        } else {
            const int* p = (const int*)faces;
            i0 = p[f*3]; i1 = p[f*3+1]; i2 = p[f*3+2];
        }
        if (s_isu64) {
            const long long* p = (const long long*)uvfaces;
            j0 = p[f*3]; j1 = p[f*3+1]; j2 = p[f*3+2];
        } else {
            const int* p = (const int*)uvfaces;
            j0 = p[f*3]; j1 = p[f*3+1]; j2 = p[f*3+2];
        }

        float ax = vertices[i0*3+0], ay = vertices[i0*3+1], az = vertices[i0*3+2];
        float bx = vertices[i1*3+0], by = vertices[i1*3+1], bz = vertices[i1*3+2];
        float cx = vertices[i2*3+0], cy = vertices[i2*3+1], cz = vertices[i2*3+2];

        // signed 2D area, LLVM-contracted: fma(d1, d2, -(d3*d4))
        float A = __fmaf_rn(__fsub_rn(bx, ax), __fsub_rn(cy, ay),
                            -__fmul_rn(__fsub_rn(by, ay), __fsub_rn(cx, ax)));
        float Asafe = (fabsf(A) < 1e-9f) ? 1.0f : A;

        float zi0 = __fdiv_rn(1.0f, az);
        float zi1 = __fdiv_rn(1.0f, bz);
        float zi2 = __fdiv_rn(1.0f, cz);

        // uvn = uv*2 - 1 contracts to fma(uv,2,-1); then * z_inv
        float u0 = __fmul_rn(__fmaf_rn(uv[j0*2+0], 2.0f, -1.0f), zi0);
        float v0 = __fmul_rn(__fmaf_rn(uv[j0*2+1], 2.0f, -1.0f), zi0);
        float u1 = __fmul_rn(__fmaf_rn(uv[j1*2+0], 2.0f, -1.0f), zi1);
        float v1 = __fmul_rn(__fmaf_rn(uv[j1*2+1], 2.0f, -1.0f), zi1);
        float u2 = __fmul_rn(__fmaf_rn(uv[j2*2+0], 2.0f, -1.0f), zi2);
        float v2 = __fmul_rn(__fmaf_rn(uv[j2*2+1], 2.0f, -1.0f), zi2);

        fd[0] = make_float4(bx, by, __fsub_rn(ay, by), __fsub_rn(ax, bx));
        fd[1] = make_float4(cx, cy, __fsub_rn(by, cy), __fsub_rn(bx, cx));
        fd[2] = make_float4(ax, ay, __fsub_rn(cy, ay), __fsub_rn(cx, ax));
        fd[3] = make_float4(Asafe, zi0, zi1, zi2);
        fd[4] = make_float4(u0, v0, u1, v1);
        fd[5] = make_float4(u2, v2, 0.f, 0.f);

        if (A >= 1e-9f) {
            // bbox pre-filter (±1 px margin)
            float minx = fminf(ax, fminf(bx, cx)), maxx = fmaxf(ax, fmaxf(bx, cx));
            float miny = fminf(ay, fminf(by, cy)), maxy = fmaxf(ay, fmaxf(by, cy));
            int jlo = max(0,   (int)floorf((minx + 1.0f) * 127.5f) - 1);
            int jhi = min(255, (int)ceilf ((maxx + 1.0f) * 127.5f) + 1);
            int klo = max(0,   (int)floorf((miny + 1.0f) * 127.5f) - 1);
            int khi = min(255, (int)ceilf ((maxy + 1.0f) * 127.5f) + 1);
            int ilo = 255 - khi, ihi = 255 - klo;
            flag = (jlo <= jt0 + 15) && (jhi >= jt0) && (ilo <= it0 + 15) && (ihi >= it0);

            if (flag) {
                // conservative tile-corner edge cull: an affine edge < -margin at
                // all 4 corners is < 0 across the tile (fp error << margin).
                const float MARGIN = -1e-3f;
                float qx0 = lin_at(jt0), qx1 = lin_at(jt0 + 15);
                float qy0 = lin_at(255 - (it0 + 15)), qy1 = lin_at(255 - it0);
                #pragma unroll
                for (int e = 0; e < 3; e++) {
                    float ex = fd[e].x, ey = fd[e].y, dy = fd[e].z, dx = fd[e].w;
                    float m = fmaxf(fmaxf(edge_at(qx0, qy0, ex, ey, dy, dx),
                                          edge_at(qx1, qy0, ex, ey, dy, dx)),
                                    fmaxf(edge_at(qx0, qy1, ex, ey, dy, dx),
                                          edge_at(qx1, qy1, ex, ey, dy, dx)));
                    if (m < MARGIN) flag = false;
                }
            }
        }
    }

    // ---- stable (index-order) compaction into sf ----
    unsigned bmask = 0;
    if (wid < 8) {
        bmask = __ballot_sync(0xffffffffu, flag);
        if (lane == 0) warpcnt[wid] = __popc(bmask);
    }
    __syncthreads();
    if (tid == 0) {
        int acc = 0;
        #pragma unroll
        for (int w = 0; w < 8; w++) { warpoff[w] = acc; acc += warpcnt[w]; }
        s_count = acc;
    }
    __syncthreads();
    if (flag) {
        int pos = warpoff[wid] + __popc(bmask & ((1u << lane) - 1u));
        #pragma unroll
        for (int q = 0; q < 6; q++) sf[pos][q] = fd[q];
    }
    __syncthreads();

    // ---- main loop: thread tz scans faces k = tz, tz+4, ... ----
    const int nf = s_count;
    const float tthr = s_tthr;
    const int j = jt0 + tx, i = it0 + ty;
    const float px = lin_at(j);
    const float py = lin_at(255 - i);   // rot90: py = lin[255-i]

    // winner = min (zinv_bits, face_idx) lexicographic  (argmax Z, first-index ties)
    unsigned long long bestkey = ~0ull;
    for (int k = tz; k < nf; k += 4) {
        float4 e0 = sf[k][0];
        float4 e1 = sf[k][1];
        float4 e2 = sf[k][2];
        float pAB = edge_at(px, py, e0.x, e0.y, e0.z, e0.w);
        float pCB = edge_at(px, py, e1.x, e1.y, e1.z, e1.w);
        float pCA = edge_at(px, py, e2.x, e2.y, e2.z, e2.w);

        if (pAB > 0.0f && pCB > 0.0f && pCA > 0.0f) {
            float4 zz = sf[k][3];   // Asafe, zi0, zi1, zi2
            float w1 = __fdiv_rn(pCB, zz.x);
            float w2 = __fdiv_rn(pCA, zz.x);
            float w3 = __fsub_rn(__fsub_rn(1.0f, w1), w2);
            float zinv = __fmaf_rn(w3, zz.w,
                         __fmaf_rn(w1, zz.y,
                         __fmul_rn(w2, zz.z)));
            // cover => zinv > 0; (Z >= zinit) <=> (zinv <= t*)
            if (zinv <= tthr) {
                unsigned long long key =
                    ((unsigned long long)__float_as_uint(zinv) << 32) | (unsigned)k;
                if (key < bestkey) bestkey = key;
            }
        }
    }
    skey[tz][ty * 16 + tx] = bestkey;
    __syncthreads();

    // ---- epilogue: tz==0 combines 4 splits, shades, stores ----
    if (tz == 0) {
        int pix = ty * 16 + tx;
        unsigned long long key = skey[0][pix];
        unsigned long long k1 = skey[1][pix]; if (k1 < key) key = k1;
        unsigned long long k2 = skey[2][pix]; if (k2 < key) key = k2;
        unsigned long long k3 = skey[3][pix]; if (k3 < key) key = k3;

        float r = 0.f, g = 0.f, b = 0.f, h = 0.f;
        if (key != ~0ull) {
            h = 1.0f;
            int bk = (int)(key & 0xFFFFFFFFull);
            float zinv = __uint_as_float((unsigned)(key >> 32));
            float Zw = __fdiv_rn(1.0f, zinv);   // == reference Zw bitwise

            float4 e1 = sf[bk][1];
            float4 e2 = sf[bk][2];
            float4 zz = sf[bk][3];
            float pCB = edge_at(px, py, e1.x, e1.y, e1.z, e1.w);
            float pCA = edge_at(px, py, e2.x, e2.y, e2.z, e2.w);
            float w1 = __fdiv_rn(pCB, zz.x);
            float w2 = __fdiv_rn(pCA, zz.x);
            float w3 = __fsub_rn(__fsub_rn(1.0f, w1), w2);

            float4 uva = sf[bk][4];
            float4 uvb = sf[bk][5];
            float u = __fmaf_rn(w3, uvb.x,
                      __fmaf_rn(w1, uva.x,
                      __fmul_rn(w2, uva.z)));
            float v = __fmaf_rn(w3, uvb.y,
                      __fmaf_rn(w1, uva.y,
                      __fmul_rn(w2, uva.w)));
            float gx = __fmul_rn(u, Zw);
            float gy = __fmul_rn(v, Zw);

            // x = ((gx+1)*256 - 1)*0.5, contracted to fma(gx+1, 256, -1)
            float x = __fmul_rn(__fmaf_rn(__fadd_rn(gx, 1.0f), 256.0f, -1.0f), 0.5f);
            float y = __fmul_rn(__fmaf_rn(__fadd_rn(gy, 1.0f), 256.0f, -1.0f), 0.5f);
            float x0 = floorf(x), y0 = floorf(y);
            float x1 = __fadd_rn(x0, 1.0f), y1 = __fadd_rn(y0, 1.0f);
            float wx1 = __fsub_rn(x, x0), wx0 = __fsub_rn(1.0f, wx1);
            float wy1 = __fsub_rn(y, y0), wy0 = __fsub_rn(1.0f, wy1);

            bool v00 = (x0 >= 0.f) && (x0 <= 255.f) && (y0 >= 0.f) && (y0 <= 255.f);
            bool v10 = (x1 >= 0.f) && (x1 <= 255.f) && (y0 >= 0.f) && (y0 <= 255.f);
            bool v01 = (x0 >= 0.f) && (x0 <= 255.f) && (y1 >= 0.f) && (y1 <= 255.f);
            bool v11 = (x1 >= 0.f) && (x1 <= 255.f) && (y1 >= 0.f) && (y1 <= 255.f);

            int ix0 = (int)fminf(fmaxf(x0, 0.f), 255.f);
            int ix1 = (int)fminf(fmaxf(x1, 0.f), 255.f);
            int iy0 = (int)fminf(fmaxf(y0, 0.f), 255.f);
            int iy1 = (int)fminf(fmaxf(y1, 0.f), 255.f);

            float w00 = __fmul_rn(wx0, wy0);
            float w10 = __fmul_rn(wx1, wy0);
            float w01 = __fmul_rn(wx0, wy1);
            float w11 = __fmul_rn(wx1, wy1);

            int o00 = iy0 * 256 + ix0, o10 = iy0 * 256 + ix1;
            int o01 = iy1 * 256 + ix0, o11 = iy1 * 256 + ix1;

            float acc[3];
            #pragma unroll
            for (int c = 0; c < 3; c++) {
                const float* img = uvmap + c * 65536;
                float t00 = v00 ? __ldg(img + o00) : 0.f;
                float t10 = v10 ? __ldg(img + o10) : 0.f;
                float t01 = v01 ? __ldg(img + o01) : 0.f;
                float t11 = v11 ? __ldg(img + o11) : 0.f;
                acc[c] = __fmaf_rn(t11, w11,
                         __fmaf_rn(t01, w01,
                         __fmaf_rn(t00, w00,
                         __fmul_rn(t10, w10))));
            }
            r = acc[0]; g = acc[1]; b = acc[2];
        }

        int pidx = i * 256 + j;
        out[0 * 65536 + pidx] = r;
        out[1 * 65536 + pidx] = g;
        out[2 * 65536 + pidx] = b;
        out[3 * 65536 + pidx] = h;
    }
}

extern "C" void kernel_launch(void* const* d_in, const int* in_sizes, int n_in,
                              void* d_out, int out_size)
{
    const float* vertices = (const float*)d_in[0];
    const void*  faces    = d_in[1];
    const float* uv       = (const float*)d_in[2];
    const void*  uvfaces  = d_in[3];
    const float* uvmap    = (const float*)d_in[4];
    float* out = (float*)d_out;

    dim3 blk(16, 16, 4), grd(IMG / 16, IMG / 16);
    render_kernel<<<grd, blk>>>(vertices, faces, uv, uvfaces, uvmap, out);
}